// round 4
// baseline (speedup 1.0000x reference)
#include <cuda_runtime.h>
#include <cstdint>

#define HID   512
#define NSTEP 8192          // BS*T = 1024*8
#define G4H   2048          // 4*HID
#define DIN   512

#define NC           128    // persistent CTAs
#define SCAN_THREADS 512
#define HC           4      // hidden indices per CTA per direction

#define BM 128
#define BN 128
#define BK 16

// Precomputed input-gate contributions, [dir][step][4H] (bias folded in)
__device__ float g_gates[(size_t)2 * NSTEP * G4H];
// Published hidden state: [parity][dir*HID+e], packed (tag<<32)|f32bits
__device__ __align__(16) unsigned long long g_hbuf[2][2 * HID];

// ---------------------------------------------------------------------------
__device__ __forceinline__ void st_rel(unsigned long long* p, unsigned long long v) {
    asm volatile("st.relaxed.gpu.global.u64 [%0], %1;" :: "l"(p), "l"(v) : "memory");
}
__device__ __forceinline__ void ld_rel_v2(const unsigned long long* p,
                                          unsigned long long& a, unsigned long long& b) {
    asm volatile("ld.relaxed.gpu.global.v2.u64 {%0, %1}, [%2];"
                 : "=l"(a), "=l"(b) : "l"(p) : "memory");
}
__device__ __forceinline__ float fast_sigmoid(float x) {
    return 1.f / (1.f + __expf(-x));
}
__device__ __forceinline__ float fast_tanh(float x) {
    return 2.f / (1.f + __expf(-2.f * x)) - 1.f;
}

// ---------------------------------------------------------------------------
// Kernel 1: gates GEMM (unchanged — measured good).
// g[dir][s][r] = dot(x_dir[s], W_ih_dir[r]) + b[r];  dir==1 row = s^7 (T=8)
// ---------------------------------------------------------------------------
__global__ __launch_bounds__(256) void gates_gemm(
    const float* __restrict__ x,
    const float* __restrict__ Wif, const float* __restrict__ bf,
    const float* __restrict__ Wib, const float* __restrict__ bb)
{
    const int dir = blockIdx.z;
    const float* __restrict__ W    = dir ? Wib : Wif;
    const float* __restrict__ bias = dir ? bb  : bf;
    float* __restrict__ out = g_gates + (size_t)dir * NSTEP * G4H;

    __shared__ __align__(16) float As[BK][BM + 4];
    __shared__ __align__(16) float Bs[BK][BN + 4];

    const int tid  = threadIdx.x;
    const int row0 = blockIdx.y * BM;
    const int col0 = blockIdx.x * BN;
    const int tx = tid & 15;
    const int ty = tid >> 4;

    float acc[8][8];
    #pragma unroll
    for (int i = 0; i < 8; i++)
        #pragma unroll
        for (int j = 0; j < 8; j++) acc[i][j] = 0.f;

    for (int k0 = 0; k0 < DIN; k0 += BK) {
        #pragma unroll
        for (int l = 0; l < 2; l++) {
            int idx = tid + l * 256;
            int m   = idx >> 2;
            int kq  = (idx & 3) * 4;
            int srow = row0 + m;
            int xrow = dir ? (srow ^ 7) : srow;
            float4 v = *(const float4*)&x[(size_t)xrow * DIN + k0 + kq];
            As[kq + 0][m] = v.x; As[kq + 1][m] = v.y;
            As[kq + 2][m] = v.z; As[kq + 3][m] = v.w;
            float4 w = *(const float4*)&W[(size_t)(col0 + m) * DIN + k0 + kq];
            Bs[kq + 0][m] = w.x; Bs[kq + 1][m] = w.y;
            Bs[kq + 2][m] = w.z; Bs[kq + 3][m] = w.w;
        }
        __syncthreads();
        #pragma unroll
        for (int kk = 0; kk < BK; kk++) {
            float a[8], b[8];
            float4 a0 = *(const float4*)&As[kk][ty * 8];
            float4 a1 = *(const float4*)&As[kk][ty * 8 + 4];
            a[0]=a0.x; a[1]=a0.y; a[2]=a0.z; a[3]=a0.w;
            a[4]=a1.x; a[5]=a1.y; a[6]=a1.z; a[7]=a1.w;
            float4 b0 = *(const float4*)&Bs[kk][tx * 8];
            float4 b1 = *(const float4*)&Bs[kk][tx * 8 + 4];
            b[0]=b0.x; b[1]=b0.y; b[2]=b0.z; b[3]=b0.w;
            b[4]=b1.x; b[5]=b1.y; b[6]=b1.z; b[7]=b1.w;
            #pragma unroll
            for (int i = 0; i < 8; i++)
                #pragma unroll
                for (int j = 0; j < 8; j++)
                    acc[i][j] = fmaf(a[i], b[j], acc[i][j]);
        }
        __syncthreads();
    }

    #pragma unroll
    for (int i = 0; i < 8; i++) {
        size_t srow = row0 + ty * 8 + i;
        #pragma unroll
        for (int j = 0; j < 8; j++) {
            int c = col0 + tx * 8 + j;
            out[srow * G4H + c] = acc[i][j] + bias[c];
        }
    }
}

// ---------------------------------------------------------------------------
// Kernel 2: persistent bidirectional scan, 2 barriers/step, plain spin poll.
// ---------------------------------------------------------------------------
__global__ void __launch_bounds__(SCAN_THREADS, 1) lstm_scan(
    const float* __restrict__ h0,
    const float* __restrict__ c0,
    const float* __restrict__ Whf,
    const float* __restrict__ Whb,
    float* __restrict__ out)
{
    __shared__ __align__(16) float sh[2][2 * HID];   // [parity][dir*HID + e]
    __shared__ __align__(16) float part[32][68];     // [dir*16+gate*4+hl][64]

    const int t   = threadIdx.x;
    const int cta = blockIdx.x;
    const int wid = t >> 5, lane = t & 31;

    // ---- matvec role ----
    const int mdir = t >> 8;           // 0 fwd / 1 bwd
    const int og   = (t >> 6) & 3;     // gate
    const int hs   = t & 63;           // h slice [hs*8, hs*8+8)
    const float* __restrict__ Wd = mdir ? Whb : Whf;
    float w[4][8];
    #pragma unroll
    for (int q = 0; q < 4; q++) {
        size_t row = (size_t)(og * HID + cta * HC + q) * HID;
        #pragma unroll
        for (int k = 0; k < 8; k++)
            w[q][k] = Wd[row + hs * 8 + k];
    }

    // ---- reduce/gates role (warps 0..7) ----
    const int rdir = wid >> 2;         // valid for wid<8
    const int hU   = wid & 3;
    const int e    = cta * HC + hU;
    const int rg   = lane >> 3;        // gate this lane reduces
    const int rrow = rdir * 16 + rg * 4 + hU;
    const int rcol = (lane & 7) * 4;
    const size_t gbase = (size_t)rdir * NSTEP * G4H + e;

    float g4[4];
    float cst = 0.f, hv = 0.f;
    if (wid < 8 && lane == 0) {
        hv  = h0[rdir * HID + e];
        cst = c0[rdir * HID + e];
        st_rel(&g_hbuf[0][rdir * HID + e],
               (1ull << 32) | (unsigned long long)__float_as_uint(hv));
        #pragma unroll
        for (int g = 0; g < 4; g++)
            g4[g] = __ldg(g_gates + gbase + (size_t)g * HID);   // step 0
    }

    for (int s = 0; s < NSTEP; s++) {
        const int p = s & 1;

        // Phase 1: spin-poll 2 slots per thread with one LDG.128
        {
            const unsigned want = (unsigned)(s + 1);
            const unsigned long long* bp = &g_hbuf[p][t * 2];
            unsigned long long v0, v1;
            do {
                ld_rel_v2(bp, v0, v1);
            } while ((unsigned)(v0 >> 32) != want || (unsigned)(v1 >> 32) != want);
            float2 hvals = make_float2(__uint_as_float((unsigned)v0),
                                       __uint_as_float((unsigned)v1));
            *(float2*)&sh[p][t * 2] = hvals;
        }
        __syncthreads();   // S1

        // Phase 2: register-tiled matvec partials
        {
            float4 ha = *(const float4*)&sh[p][mdir * HID + hs * 8];
            float4 hb = *(const float4*)&sh[p][mdir * HID + hs * 8 + 4];
            float hr[8] = {ha.x, ha.y, ha.z, ha.w, hb.x, hb.y, hb.z, hb.w};
            float a0 = 0.f, a1 = 0.f, a2 = 0.f, a3 = 0.f;
            #pragma unroll
            for (int k = 0; k < 8; k++) {
                float h = hr[k];
                a0 = fmaf(w[0][k], h, a0);
                a1 = fmaf(w[1][k], h, a1);
                a2 = fmaf(w[2][k], h, a2);
                a3 = fmaf(w[3][k], h, a3);
            }
            int prow = (mdir << 4) + (og << 2);
            part[prow + 0][hs] = a0;
            part[prow + 1][hs] = a1;
            part[prow + 2][hs] = a2;
            part[prow + 3][hs] = a3;
        }
        __syncthreads();   // S2

        // Phase 3: warp-local reduce + gates + publish (warps 0..7)
        if (wid < 8) {
            float4 pa = *(const float4*)&part[rrow][rcol];
            float4 pb = *(const float4*)&part[rrow][rcol + 32];
            float sv = ((pa.x + pa.y) + (pa.z + pa.w))
                     + ((pb.x + pb.y) + (pb.z + pb.w));
            sv += __shfl_xor_sync(0xffffffffu, sv, 1);
            sv += __shfl_xor_sync(0xffffffffu, sv, 2);
            sv += __shfl_xor_sync(0xffffffffu, sv, 4);
            float z0 = __shfl_sync(0xffffffffu, sv, 0);
            float z1 = __shfl_sync(0xffffffffu, sv, 8);
            float z2 = __shfl_sync(0xffffffffu, sv, 16);
            float z3 = __shfl_sync(0xffffffffu, sv, 24);

            if (lane == 0) {
                float zi = z0 + g4[0];
                float zf = z1 + g4[1];
                float zg = z2 + g4[2];
                float zo = z3 + g4[3];
                float ig = fast_sigmoid(zi);
                float fg = fast_sigmoid(zf);
                float gg = fast_tanh(zg);
                float oo = fast_sigmoid(zo);
                cst = fmaf(fg, cst, ig * gg);
                hv  = oo * fast_tanh(cst);

                st_rel(&g_hbuf[p ^ 1][rdir * HID + e],
                       (((unsigned long long)(unsigned)(s + 2)) << 32) |
                       (unsigned long long)__float_as_uint(hv));

                size_t orow = rdir ? (size_t)(s ^ 7) : (size_t)s;
                out[orow * (2 * HID) + rdir * HID + e] = hv;

                if (s == NSTEP - 1) {
                    out[(size_t)NSTEP * 2 * HID + rdir * HID + e] = hv;
                    out[(size_t)NSTEP * 2 * HID + 2 * HID + rdir * HID + e] = cst;
                } else {
                    size_t nb = gbase + (size_t)(s + 1) * G4H;
                    #pragma unroll
                    for (int g = 0; g < 4; g++)
                        g4[g] = __ldg(g_gates + nb + (size_t)g * HID);
                }
            }
        }
        // next-step S1 protects part[] reuse; sh is parity double-buffered
    }
}

// ---------------------------------------------------------------------------
extern "C" void kernel_launch(void* const* d_in, const int* in_sizes, int n_in,
                              void* d_out, int out_size)
{
    const float* x   = (const float*)d_in[0];
    const float* h0  = (const float*)d_in[1];
    const float* c0  = (const float*)d_in[2];
    const float* Wif = (const float*)d_in[3];
    const float* Whf = (const float*)d_in[4];
    const float* bf  = (const float*)d_in[5];
    const float* Wib = (const float*)d_in[6];
    const float* Whb = (const float*)d_in[7];
    const float* bb  = (const float*)d_in[8];
    float* out = (float*)d_out;

    dim3 ggrid(G4H / BN, NSTEP / BM, 2);
    gates_gemm<<<ggrid, 256>>>(x, Wif, bf, Wib, bb);
    lstm_scan<<<NC, SCAN_THREADS>>>(h0, c0, Whf, Whb, out);
}

// round 5
// speedup vs baseline: 2.9363x; 2.9363x over previous
#include <cuda_runtime.h>
#include <cstdint>

// Problem constants
#define HID   512
#define NSTEP 8192          // BS*T = 1024*8
#define G4H   2048          // 4*HID
#define DIN   512

// Scan kernel config
#define NC           128    // persistent CTAs
#define SCAN_THREADS 512
#define HC           4      // hidden indices per CTA per direction (128*4 = 512)

// GEMM config
#define BM 128
#define BN 128
#define BK 16

// Scratch: precomputed input-gate contributions, [dir][step][4H]  (128 MB)
__device__ float g_gates[(size_t)2 * NSTEP * G4H];
// Published hidden state: [dir][parity][elem] packed as (tag<<32)|f32bits
__device__ unsigned long long g_hbuf[2][2][HID];

// ---------------------------------------------------------------------------
__device__ __forceinline__ void st_rel(unsigned long long* p, unsigned long long v) {
    asm volatile("st.global.relaxed.gpu.u64 [%0], %1;" :: "l"(p), "l"(v) : "memory");
}
__device__ __forceinline__ unsigned long long ld_rel(const unsigned long long* p) {
    unsigned long long v;
    asm volatile("ld.global.relaxed.gpu.u64 %0, [%1];" : "=l"(v) : "l"(p) : "memory");
    return v;
}
__device__ __forceinline__ float fast_sigmoid(float x) {
    return 1.f / (1.f + __expf(-x));
}
__device__ __forceinline__ float fast_tanh(float x) {
    return 2.f / (1.f + __expf(-2.f * x)) - 1.f;
}

// ---------------------------------------------------------------------------
// Kernel 1: gates GEMM.  g[dir][s][r] = dot(x_dir[s], W_ih_dir[r]) + b[r]
// dir==1 uses per-sample time reversal: x row = s ^ 7  (T=8)
// ---------------------------------------------------------------------------
__global__ __launch_bounds__(256) void gates_gemm(
    const float* __restrict__ x,
    const float* __restrict__ Wif, const float* __restrict__ bf,
    const float* __restrict__ Wib, const float* __restrict__ bb)
{
    const int dir = blockIdx.z;
    const float* __restrict__ W    = dir ? Wib : Wif;
    const float* __restrict__ bias = dir ? bb  : bf;
    float* __restrict__ out = g_gates + (size_t)dir * NSTEP * G4H;

    __shared__ __align__(16) float As[BK][BM + 4];
    __shared__ __align__(16) float Bs[BK][BN + 4];

    const int tid  = threadIdx.x;          // 0..255
    const int row0 = blockIdx.y * BM;      // step rows
    const int col0 = blockIdx.x * BN;      // gate rows
    const int tx = tid & 15;               // 16x16 thread grid, 8x8 tiles
    const int ty = tid >> 4;

    float acc[8][8];
    #pragma unroll
    for (int i = 0; i < 8; i++)
        #pragma unroll
        for (int j = 0; j < 8; j++) acc[i][j] = 0.f;

    for (int k0 = 0; k0 < DIN; k0 += BK) {
        #pragma unroll
        for (int l = 0; l < 2; l++) {
            int idx = tid + l * 256;          // 0..511
            int m   = idx >> 2;               // 0..127
            int kq  = (idx & 3) * 4;          // 0,4,8,12
            int srow = row0 + m;
            int xrow = dir ? (srow ^ 7) : srow;
            float4 v = *(const float4*)&x[(size_t)xrow * DIN + k0 + kq];
            As[kq + 0][m] = v.x; As[kq + 1][m] = v.y;
            As[kq + 2][m] = v.z; As[kq + 3][m] = v.w;
            float4 w = *(const float4*)&W[(size_t)(col0 + m) * DIN + k0 + kq];
            Bs[kq + 0][m] = w.x; Bs[kq + 1][m] = w.y;
            Bs[kq + 2][m] = w.z; Bs[kq + 3][m] = w.w;
        }
        __syncthreads();
        #pragma unroll
        for (int kk = 0; kk < BK; kk++) {
            float a[8], b[8];
            float4 a0 = *(const float4*)&As[kk][ty * 8];
            float4 a1 = *(const float4*)&As[kk][ty * 8 + 4];
            a[0]=a0.x; a[1]=a0.y; a[2]=a0.z; a[3]=a0.w;
            a[4]=a1.x; a[5]=a1.y; a[6]=a1.z; a[7]=a1.w;
            float4 b0 = *(const float4*)&Bs[kk][tx * 8];
            float4 b1 = *(const float4*)&Bs[kk][tx * 8 + 4];
            b[0]=b0.x; b[1]=b0.y; b[2]=b0.z; b[3]=b0.w;
            b[4]=b1.x; b[5]=b1.y; b[6]=b1.z; b[7]=b1.w;
            #pragma unroll
            for (int i = 0; i < 8; i++)
                #pragma unroll
                for (int j = 0; j < 8; j++)
                    acc[i][j] = fmaf(a[i], b[j], acc[i][j]);
        }
        __syncthreads();
    }

    #pragma unroll
    for (int i = 0; i < 8; i++) {
        size_t srow = row0 + ty * 8 + i;
        #pragma unroll
        for (int j = 0; j < 8; j++) {
            int c = col0 + tx * 8 + j;
            out[srow * G4H + c] = acc[i][j] + bias[c];
        }
    }
}

// ---------------------------------------------------------------------------
// Kernel 2: persistent bidirectional LSTM scan — EXACT R1 structure
// (3 barriers, same poll, same reduce). Only change: fast_tanh/fast_sigmoid
// in phase 4 instead of tanhf / 1/(1+__expf).
// ---------------------------------------------------------------------------
__global__ void __launch_bounds__(SCAN_THREADS, 1) lstm_scan(
    const float* __restrict__ h0,
    const float* __restrict__ c0,
    const float* __restrict__ Whf,
    const float* __restrict__ Whb,
    float* __restrict__ out)
{
    const int cta = blockIdx.x;   // 0..127
    const int tid = threadIdx.x;  // 0..511

    __shared__ __align__(16) float sh[2][HID];      // polled hidden state
    __shared__ __align__(16) float part[32][64];    // matvec partials
    __shared__ float zbuf[32];                      // reduced z per (dir,gate,hl)

    // ---- matvec role: dir, output-group (== gate), h-slice ----
    const int dir = tid >> 8;          // 0 fwd / 1 bwd
    const int r   = tid & 255;
    const int og  = r >> 6;            // gate 0..3 (i,f,g,o)
    const int hs  = r & 63;            // h slice [hs*8, hs*8+8)

    const float* __restrict__ Wd = dir ? Whb : Whf;
    float w[4][8];                     // 4 outputs (hl=0..3) x 8 h-elems
    #pragma unroll
    for (int q = 0; q < 4; q++) {
        size_t row = (size_t)og * HID + cta * HC + q;
        #pragma unroll
        for (int k = 0; k < 8; k++)
            w[q][k] = Wd[row * HID + hs * 8 + k];
    }

    // ---- reduce role ----
    const int row  = tid >> 4;          // 0..31 = dir*16 + gate*4 + hl
    const int sub  = tid & 15;
    const int rd   = row >> 4;
    const int rlr  = row & 15;
    const size_t gq_base = (size_t)rd * NSTEP * G4H
                         + (size_t)(rlr >> 2) * HID + cta * HC + (rlr & 3);
    float gcur = 0.f;
    if (sub == 0) gcur = __ldg(g_gates + gq_base);   // step 0 gate contribution

    // ---- poll role: 2 consecutive elements per thread ----
    const int pd = tid >> 8;
    const int pi = (tid & 255) * 2;

    // ---- update role (tid<8): owns c state, publishes h ----
    float cst = 0.f, hv = 0.f;
    if (tid < 8) {
        int dU = tid >> 2, hU = tid & 3;
        int e  = cta * HC + hU;
        hv  = h0[dU * HID + e];
        cst = c0[dU * HID + e];
        unsigned long long pk =
            (((unsigned long long)1u) << 32) | (unsigned long long)__float_as_uint(hv);
        st_rel(&g_hbuf[dU][0][e], pk);   // publish h0 with tag 1 into parity 0
    }

    for (int s = 0; s < NSTEP; s++) {
        // Phase 1: poll the full hidden vector (both dirs) into smem
        {
            const unsigned want = (unsigned)(s + 1);
            const unsigned long long* base = &g_hbuf[pd][s & 1][pi];
            unsigned long long v0, v1;
            do { v0 = ld_rel(base);     } while ((unsigned)(v0 >> 32) != want);
            do { v1 = ld_rel(base + 1); } while ((unsigned)(v1 >> 32) != want);
            sh[pd][pi]     = __uint_as_float((unsigned)v0);
            sh[pd][pi + 1] = __uint_as_float((unsigned)v1);
        }
        __syncthreads();   // S1

        // Phase 2: register-tiled matvec partials
        {
            float4 ha = *(const float4*)&sh[dir][hs * 8];
            float4 hb = *(const float4*)&sh[dir][hs * 8 + 4];
            float hr[8] = {ha.x, ha.y, ha.z, ha.w, hb.x, hb.y, hb.z, hb.w};
            float a0 = 0.f, a1 = 0.f, a2 = 0.f, a3 = 0.f;
            #pragma unroll
            for (int k = 0; k < 8; k++) {
                float h = hr[k];
                a0 = fmaf(w[0][k], h, a0);
                a1 = fmaf(w[1][k], h, a1);
                a2 = fmaf(w[2][k], h, a2);
                a3 = fmaf(w[3][k], h, a3);
            }
            int prow = (dir << 4) + (og << 2);
            part[prow + 0][hs] = a0;
            part[prow + 1][hs] = a1;
            part[prow + 2][hs] = a2;
            part[prow + 3][hs] = a3;
        }
        __syncthreads();   // S2

        // Phase 3: reduce 64 partials per output (16 lanes x 4 + shfl tree)
        {
            float4 p = *(const float4*)&part[row][sub << 2];
            float sv = (p.x + p.y) + (p.z + p.w);
            sv += __shfl_xor_sync(0xffffffffu, sv, 1);
            sv += __shfl_xor_sync(0xffffffffu, sv, 2);
            sv += __shfl_xor_sync(0xffffffffu, sv, 4);
            sv += __shfl_xor_sync(0xffffffffu, sv, 8);
            if (sub == 0) {
                zbuf[row] = sv + gcur;
                int ns = (s + 1 < NSTEP) ? (s + 1) : (NSTEP - 1);
                gcur = __ldg(g_gates + gq_base + (size_t)ns * G4H);  // prefetch
            }
        }
        __syncthreads();   // S3

        // Phase 4: gate nonlinearities, state update, publish + store output
        if (tid < 8) {
            int dU = tid >> 2, hU = tid & 3;
            int zb = dU << 4;
            float zi = zbuf[zb + hU];
            float zf = zbuf[zb + 4 + hU];
            float zg = zbuf[zb + 8 + hU];
            float zo = zbuf[zb + 12 + hU];
            float ig = fast_sigmoid(zi);
            float fg = fast_sigmoid(zf);
            float gg = fast_tanh(zg);
            float oo = fast_sigmoid(zo);
            cst = fmaf(fg, cst, ig * gg);
            hv  = oo * fast_tanh(cst);

            int e = cta * HC + hU;
            unsigned long long pk =
                (((unsigned long long)(unsigned)(s + 2)) << 32) |
                (unsigned long long)__float_as_uint(hv);
            st_rel(&g_hbuf[dU][(s + 1) & 1][e], pk);

            size_t orow = dU ? (size_t)(s ^ 7) : (size_t)s;   // bwd un-reverses time
            out[orow * (2 * HID) + dU * HID + e] = hv;

            if (s == NSTEP - 1) {
                out[(size_t)NSTEP * 2 * HID + dU * HID + e] = hv;            // h_n
                out[(size_t)NSTEP * 2 * HID + 2 * HID + dU * HID + e] = cst; // c_n
            }
        }
        // no extra sync needed: S1 of the next step protects zbuf/sh reuse
    }
}

// ---------------------------------------------------------------------------
extern "C" void kernel_launch(void* const* d_in, const int* in_sizes, int n_in,
                              void* d_out, int out_size)
{
    const float* x   = (const float*)d_in[0];
    const float* h0  = (const float*)d_in[1];
    const float* c0  = (const float*)d_in[2];
    const float* Wif = (const float*)d_in[3];
    const float* Whf = (const float*)d_in[4];
    const float* bf  = (const float*)d_in[5];
    const float* Wib = (const float*)d_in[6];
    const float* Whb = (const float*)d_in[7];
    const float* bb  = (const float*)d_in[8];
    float* out = (float*)d_out;

    dim3 ggrid(G4H / BN, NSTEP / BM, 2);
    gates_gemm<<<ggrid, 256>>>(x, Wif, bf, Wib, bb);
    lstm_scan<<<NC, SCAN_THREADS>>>(h0, c0, Whf, Whb, out);
}

// round 6
// speedup vs baseline: 3.2356x; 1.1019x over previous
#include <cuda_runtime.h>
#include <cstdint>

// Problem constants
#define HID   512
#define NSTEP 8192          // BS*T = 1024*8
#define G4H   2048          // 4*HID
#define DIN   512

// Scan kernel config
#define NC           128
#define SCAN_THREADS 512
#define HC           4

// GEMM config
#define BM 128
#define BN 128
#define BK 16

__device__ float g_gates[(size_t)2 * NSTEP * G4H];
__device__ unsigned long long g_hbuf[2][2][HID];

// ---------------------------------------------------------------------------
__device__ __forceinline__ void st_rel(unsigned long long* p, unsigned long long v) {
    asm volatile("st.global.relaxed.gpu.u64 [%0], %1;" :: "l"(p), "l"(v) : "memory");
}
__device__ __forceinline__ unsigned long long ld_rel(const unsigned long long* p) {
    unsigned long long v;
    asm volatile("ld.global.relaxed.gpu.u64 %0, [%1];" : "=l"(v) : "l"(p) : "memory");
    return v;
}
// MUFU-only transcendentals: EX2 + RCP, no slow div on the serial path.
__device__ __forceinline__ float fast_sigmoid(float x) {
    return __fdividef(1.f, 1.f + __expf(-x));
}
__device__ __forceinline__ float fast_tanh(float x) {
    return __fdividef(2.f, 1.f + __expf(-2.f * x)) - 1.f;
}

// ---------------------------------------------------------------------------
// Kernel 1: gates GEMM (unchanged — measured good).
// ---------------------------------------------------------------------------
__global__ __launch_bounds__(256) void gates_gemm(
    const float* __restrict__ x,
    const float* __restrict__ Wif, const float* __restrict__ bf,
    const float* __restrict__ Wib, const float* __restrict__ bb)
{
    const int dir = blockIdx.z;
    const float* __restrict__ W    = dir ? Wib : Wif;
    const float* __restrict__ bias = dir ? bb  : bf;
    float* __restrict__ out = g_gates + (size_t)dir * NSTEP * G4H;

    __shared__ __align__(16) float As[BK][BM + 4];
    __shared__ __align__(16) float Bs[BK][BN + 4];

    const int tid  = threadIdx.x;
    const int row0 = blockIdx.y * BM;
    const int col0 = blockIdx.x * BN;
    const int tx = tid & 15;
    const int ty = tid >> 4;

    float acc[8][8];
    #pragma unroll
    for (int i = 0; i < 8; i++)
        #pragma unroll
        for (int j = 0; j < 8; j++) acc[i][j] = 0.f;

    for (int k0 = 0; k0 < DIN; k0 += BK) {
        #pragma unroll
        for (int l = 0; l < 2; l++) {
            int idx = tid + l * 256;
            int m   = idx >> 2;
            int kq  = (idx & 3) * 4;
            int srow = row0 + m;
            int xrow = dir ? (srow ^ 7) : srow;
            float4 v = *(const float4*)&x[(size_t)xrow * DIN + k0 + kq];
            As[kq + 0][m] = v.x; As[kq + 1][m] = v.y;
            As[kq + 2][m] = v.z; As[kq + 3][m] = v.w;
            float4 w = *(const float4*)&W[(size_t)(col0 + m) * DIN + k0 + kq];
            Bs[kq + 0][m] = w.x; Bs[kq + 1][m] = w.y;
            Bs[kq + 2][m] = w.z; Bs[kq + 3][m] = w.w;
        }
        __syncthreads();
        #pragma unroll
        for (int kk = 0; kk < BK; kk++) {
            float a[8], b[8];
            float4 a0 = *(const float4*)&As[kk][ty * 8];
            float4 a1 = *(const float4*)&As[kk][ty * 8 + 4];
            a[0]=a0.x; a[1]=a0.y; a[2]=a0.z; a[3]=a0.w;
            a[4]=a1.x; a[5]=a1.y; a[6]=a1.z; a[7]=a1.w;
            float4 b0 = *(const float4*)&Bs[kk][tx * 8];
            float4 b1 = *(const float4*)&Bs[kk][tx * 8 + 4];
            b[0]=b0.x; b[1]=b0.y; b[2]=b0.z; b[3]=b0.w;
            b[4]=b1.x; b[5]=b1.y; b[6]=b1.z; b[7]=b1.w;
            #pragma unroll
            for (int i = 0; i < 8; i++)
                #pragma unroll
                for (int j = 0; j < 8; j++)
                    acc[i][j] = fmaf(a[i], b[j], acc[i][j]);
        }
        __syncthreads();
    }

    #pragma unroll
    for (int i = 0; i < 8; i++) {
        size_t srow = row0 + ty * 8 + i;
        #pragma unroll
        for (int j = 0; j < 8; j++) {
            int c = col0 + tx * 8 + j;
            out[srow * G4H + c] = acc[i][j] + bias[c];
        }
    }
}

// ---------------------------------------------------------------------------
// Kernel 2: R1 structure + (a) MUFU-only gates, (b) S4 after publish.
// ---------------------------------------------------------------------------
__global__ void __launch_bounds__(SCAN_THREADS, 1) lstm_scan(
    const float* __restrict__ h0,
    const float* __restrict__ c0,
    const float* __restrict__ Whf,
    const float* __restrict__ Whb,
    float* __restrict__ out)
{
    const int cta = blockIdx.x;
    const int tid = threadIdx.x;

    __shared__ __align__(16) float sh[2][HID];
    __shared__ __align__(16) float part[32][64];
    __shared__ float zbuf[32];

    // ---- matvec role ----
    const int dir = tid >> 8;
    const int r   = tid & 255;
    const int og  = r >> 6;
    const int hs  = r & 63;

    const float* __restrict__ Wd = dir ? Whb : Whf;
    float w[4][8];
    #pragma unroll
    for (int q = 0; q < 4; q++) {
        size_t row = (size_t)og * HID + cta * HC + q;
        #pragma unroll
        for (int k = 0; k < 8; k++)
            w[q][k] = Wd[row * HID + hs * 8 + k];
    }

    // ---- reduce role ----
    const int row  = tid >> 4;
    const int sub  = tid & 15;
    const int rd   = row >> 4;
    const int rlr  = row & 15;
    const size_t gq_base = (size_t)rd * NSTEP * G4H
                         + (size_t)(rlr >> 2) * HID + cta * HC + (rlr & 3);
    float gcur = 0.f;
    if (sub == 0) gcur = __ldg(g_gates + gq_base);

    // ---- poll role ----
    const int pd = tid >> 8;
    const int pi = (tid & 255) * 2;

    // ---- update role (tid<8) ----
    float cst = 0.f, hv = 0.f;
    if (tid < 8) {
        int dU = tid >> 2, hU = tid & 3;
        int e  = cta * HC + hU;
        hv  = h0[dU * HID + e];
        cst = c0[dU * HID + e];
        unsigned long long pk =
            (((unsigned long long)1u) << 32) | (unsigned long long)__float_as_uint(hv);
        st_rel(&g_hbuf[dU][0][e], pk);
    }

    for (int s = 0; s < NSTEP; s++) {
        // Phase 1: poll the full hidden vector (both dirs) into smem
        {
            const unsigned want = (unsigned)(s + 1);
            const unsigned long long* base = &g_hbuf[pd][s & 1][pi];
            unsigned long long v0, v1;
            do { v0 = ld_rel(base);     } while ((unsigned)(v0 >> 32) != want);
            do { v1 = ld_rel(base + 1); } while ((unsigned)(v1 >> 32) != want);
            sh[pd][pi]     = __uint_as_float((unsigned)v0);
            sh[pd][pi + 1] = __uint_as_float((unsigned)v1);
        }
        __syncthreads();   // S1

        // Phase 2: register-tiled matvec partials
        {
            float4 ha = *(const float4*)&sh[dir][hs * 8];
            float4 hb = *(const float4*)&sh[dir][hs * 8 + 4];
            float hr[8] = {ha.x, ha.y, ha.z, ha.w, hb.x, hb.y, hb.z, hb.w};
            float a0 = 0.f, a1 = 0.f, a2 = 0.f, a3 = 0.f;
            #pragma unroll
            for (int k = 0; k < 8; k++) {
                float h = hr[k];
                a0 = fmaf(w[0][k], h, a0);
                a1 = fmaf(w[1][k], h, a1);
                a2 = fmaf(w[2][k], h, a2);
                a3 = fmaf(w[3][k], h, a3);
            }
            int prow = (dir << 4) + (og << 2);
            part[prow + 0][hs] = a0;
            part[prow + 1][hs] = a1;
            part[prow + 2][hs] = a2;
            part[prow + 3][hs] = a3;
        }
        __syncthreads();   // S2

        // Phase 3: reduce partials
        {
            float4 p = *(const float4*)&part[row][sub << 2];
            float sv = (p.x + p.y) + (p.z + p.w);
            sv += __shfl_xor_sync(0xffffffffu, sv, 1);
            sv += __shfl_xor_sync(0xffffffffu, sv, 2);
            sv += __shfl_xor_sync(0xffffffffu, sv, 4);
            sv += __shfl_xor_sync(0xffffffffu, sv, 8);
            if (sub == 0) zbuf[row] = sv + gcur;
        }
        __syncthreads();   // S3

        // Phase 4: gates + state update + PUBLISH (owners only)
        if (tid < 8) {
            int dU = tid >> 2, hU = tid & 3;
            int zb = dU << 4;
            float zi = zbuf[zb + hU];
            float zf = zbuf[zb + 4 + hU];
            float zg = zbuf[zb + 8 + hU];
            float zo = zbuf[zb + 12 + hU];
            float ig = fast_sigmoid(zi);
            float fg = fast_sigmoid(zf);
            float gg = fast_tanh(zg);
            float oo = fast_sigmoid(zo);
            cst = fmaf(fg, cst, ig * gg);
            hv  = oo * fast_tanh(cst);

            int e = cta * HC + hU;
            unsigned long long pk =
                (((unsigned long long)(unsigned)(s + 2)) << 32) |
                (unsigned long long)__float_as_uint(hv);
            st_rel(&g_hbuf[dU][(s + 1) & 1][e], pk);
        }
        __syncthreads();   // S4 — hold poll flood until all publishes issued

        // Phase 5 (off critical path): output store + next gate prefetch
        if (tid < 8) {
            int dU = tid >> 2, hU = tid & 3;
            int e  = cta * HC + hU;
            size_t orow = dU ? (size_t)(s ^ 7) : (size_t)s;
            out[orow * (2 * HID) + dU * HID + e] = hv;
            if (s == NSTEP - 1) {
                out[(size_t)NSTEP * 2 * HID + dU * HID + e] = hv;
                out[(size_t)NSTEP * 2 * HID + 2 * HID + dU * HID + e] = cst;
            }
        }
        if (sub == 0) {
            int ns = (s + 1 < NSTEP) ? (s + 1) : (NSTEP - 1);
            gcur = __ldg(g_gates + gq_base + (size_t)ns * G4H);
        }
    }
}

// ---------------------------------------------------------------------------
extern "C" void kernel_launch(void* const* d_in, const int* in_sizes, int n_in,
                              void* d_out, int out_size)
{
    const float* x   = (const float*)d_in[0];
    const float* h0  = (const float*)d_in[1];
    const float* c0  = (const float*)d_in[2];
    const float* Wif = (const float*)d_in[3];
    const float* Whf = (const float*)d_in[4];
    const float* bf  = (const float*)d_in[5];
    const float* Wib = (const float*)d_in[6];
    const float* Whb = (const float*)d_in[7];
    const float* bb  = (const float*)d_in[8];
    float* out = (float*)d_out;

    dim3 ggrid(G4H / BN, NSTEP / BM, 2);
    gates_gemm<<<ggrid, 256>>>(x, Wif, bf, Wib, bb);
    lstm_scan<<<NC, SCAN_THREADS>>>(h0, c0, Whf, Whb, out);
}

// round 7
// speedup vs baseline: 3.8058x; 1.1762x over previous
#include <cuda_runtime.h>
#include <cstdint>

// Problem constants
#define HID   512
#define NSTEP 8192          // BS*T = 1024*8
#define G4H   2048          // 4*HID
#define DIN   512

// Scan kernel config
#define NC           128
#define SCAN_THREADS 512
#define HC           4

// GEMM config
#define BM 128
#define BN 128
#define BK 16

__device__ float g_gates[(size_t)2 * NSTEP * G4H];
__device__ __align__(128) unsigned long long g_hbuf[2][2][HID];

// ---------------------------------------------------------------------------
__device__ __forceinline__ void st_rel(unsigned long long* p, unsigned long long v) {
    asm volatile("st.global.relaxed.gpu.u64 [%0], %1;" :: "l"(p), "l"(v) : "memory");
}
__device__ __forceinline__ void ld_rel_v2(const unsigned long long* p,
                                          unsigned long long& a, unsigned long long& b) {
    asm volatile("ld.relaxed.gpu.global.v2.u64 {%0, %1}, [%2];"
                 : "=l"(a), "=l"(b) : "l"(p) : "memory");
}
// Hardware tanh (MUFU.TANH, sm_75+): one op per transcendental.
__device__ __forceinline__ float htanh(float x) {
    float y;
    asm("tanh.approx.f32 %0, %1;" : "=f"(y) : "f"(x));
    return y;
}
__device__ __forceinline__ float hsigmoid(float x) {
    return fmaf(htanh(0.5f * x), 0.5f, 0.5f);
}

// ---------------------------------------------------------------------------
// Kernel 1: gates GEMM (unchanged — measured good).
// ---------------------------------------------------------------------------
__global__ __launch_bounds__(256) void gates_gemm(
    const float* __restrict__ x,
    const float* __restrict__ Wif, const float* __restrict__ bf,
    const float* __restrict__ Wib, const float* __restrict__ bb)
{
    const int dir = blockIdx.z;
    const float* __restrict__ W    = dir ? Wib : Wif;
    const float* __restrict__ bias = dir ? bb  : bf;
    float* __restrict__ out = g_gates + (size_t)dir * NSTEP * G4H;

    __shared__ __align__(16) float As[BK][BM + 4];
    __shared__ __align__(16) float Bs[BK][BN + 4];

    const int tid  = threadIdx.x;
    const int row0 = blockIdx.y * BM;
    const int col0 = blockIdx.x * BN;
    const int tx = tid & 15;
    const int ty = tid >> 4;

    float acc[8][8];
    #pragma unroll
    for (int i = 0; i < 8; i++)
        #pragma unroll
        for (int j = 0; j < 8; j++) acc[i][j] = 0.f;

    for (int k0 = 0; k0 < DIN; k0 += BK) {
        #pragma unroll
        for (int l = 0; l < 2; l++) {
            int idx = tid + l * 256;
            int m   = idx >> 2;
            int kq  = (idx & 3) * 4;
            int srow = row0 + m;
            int xrow = dir ? (srow ^ 7) : srow;
            float4 v = *(const float4*)&x[(size_t)xrow * DIN + k0 + kq];
            As[kq + 0][m] = v.x; As[kq + 1][m] = v.y;
            As[kq + 2][m] = v.z; As[kq + 3][m] = v.w;
            float4 w = *(const float4*)&W[(size_t)(col0 + m) * DIN + k0 + kq];
            Bs[kq + 0][m] = w.x; Bs[kq + 1][m] = w.y;
            Bs[kq + 2][m] = w.z; Bs[kq + 3][m] = w.w;
        }
        __syncthreads();
        #pragma unroll
        for (int kk = 0; kk < BK; kk++) {
            float a[8], b[8];
            float4 a0 = *(const float4*)&As[kk][ty * 8];
            float4 a1 = *(const float4*)&As[kk][ty * 8 + 4];
            a[0]=a0.x; a[1]=a0.y; a[2]=a0.z; a[3]=a0.w;
            a[4]=a1.x; a[5]=a1.y; a[6]=a1.z; a[7]=a1.w;
            float4 b0 = *(const float4*)&Bs[kk][tx * 8];
            float4 b1 = *(const float4*)&Bs[kk][tx * 8 + 4];
            b[0]=b0.x; b[1]=b0.y; b[2]=b0.z; b[3]=b0.w;
            b[4]=b1.x; b[5]=b1.y; b[6]=b1.z; b[7]=b1.w;
            #pragma unroll
            for (int i = 0; i < 8; i++)
                #pragma unroll
                for (int j = 0; j < 8; j++)
                    acc[i][j] = fmaf(a[i], b[j], acc[i][j]);
        }
        __syncthreads();
    }

    #pragma unroll
    for (int i = 0; i < 8; i++) {
        size_t srow = row0 + ty * 8 + i;
        #pragma unroll
        for (int j = 0; j < 8; j++) {
            int c = col0 + tx * 8 + j;
            out[srow * G4H + c] = acc[i][j] + bias[c];
        }
    }
}

// ---------------------------------------------------------------------------
// Kernel 2: R6 structure (4 barriers) + vectorized poll + MUFU.TANH gates.
// ---------------------------------------------------------------------------
__global__ void __launch_bounds__(SCAN_THREADS, 1) lstm_scan(
    const float* __restrict__ h0,
    const float* __restrict__ c0,
    const float* __restrict__ Whf,
    const float* __restrict__ Whb,
    float* __restrict__ out)
{
    const int cta = blockIdx.x;
    const int tid = threadIdx.x;

    __shared__ __align__(16) float sh[2][HID];
    __shared__ __align__(16) float part[32][64];
    __shared__ float zbuf[32];

    // ---- matvec role ----
    const int dir = tid >> 8;
    const int r   = tid & 255;
    const int og  = r >> 6;
    const int hs  = r & 63;

    const float* __restrict__ Wd = dir ? Whb : Whf;
    float w[4][8];
    #pragma unroll
    for (int q = 0; q < 4; q++) {
        size_t row = (size_t)og * HID + cta * HC + q;
        #pragma unroll
        for (int k = 0; k < 8; k++)
            w[q][k] = Wd[row * HID + hs * 8 + k];
    }

    // ---- reduce role ----
    const int row  = tid >> 4;
    const int sub  = tid & 15;
    const int rd   = row >> 4;
    const int rlr  = row & 15;
    const size_t gq_base = (size_t)rd * NSTEP * G4H
                         + (size_t)(rlr >> 2) * HID + cta * HC + (rlr & 3);
    float gcur = 0.f;
    if (sub == 0) gcur = __ldg(g_gates + gq_base);

    // ---- poll role ----
    const int pd = tid >> 8;
    const int pi = (tid & 255) * 2;

    // ---- update role (tid<8) ----
    float cst = 0.f, hv = 0.f;
    if (tid < 8) {
        int dU = tid >> 2, hU = tid & 3;
        int e  = cta * HC + hU;
        hv  = h0[dU * HID + e];
        cst = c0[dU * HID + e];
        unsigned long long pk =
            (((unsigned long long)1u) << 32) | (unsigned long long)__float_as_uint(hv);
        st_rel(&g_hbuf[dU][0][e], pk);
    }

    for (int s = 0; s < NSTEP; s++) {
        // Phase 1: poll 2 slots per thread with one LDG.128
        {
            const unsigned want = (unsigned)(s + 1);
            const unsigned long long* base = &g_hbuf[pd][s & 1][pi];
            unsigned long long v0, v1;
            do {
                ld_rel_v2(base, v0, v1);
            } while ((unsigned)(v0 >> 32) != want || (unsigned)(v1 >> 32) != want);
            float2 hvals = make_float2(__uint_as_float((unsigned)v0),
                                       __uint_as_float((unsigned)v1));
            *(float2*)&sh[pd][pi] = hvals;
        }
        __syncthreads();   // S1

        // Phase 2: register-tiled matvec partials
        {
            float4 ha = *(const float4*)&sh[dir][hs * 8];
            float4 hb = *(const float4*)&sh[dir][hs * 8 + 4];
            float hr[8] = {ha.x, ha.y, ha.z, ha.w, hb.x, hb.y, hb.z, hb.w};
            float a0 = 0.f, a1 = 0.f, a2 = 0.f, a3 = 0.f;
            #pragma unroll
            for (int k = 0; k < 8; k++) {
                float h = hr[k];
                a0 = fmaf(w[0][k], h, a0);
                a1 = fmaf(w[1][k], h, a1);
                a2 = fmaf(w[2][k], h, a2);
                a3 = fmaf(w[3][k], h, a3);
            }
            int prow = (dir << 4) + (og << 2);
            part[prow + 0][hs] = a0;
            part[prow + 1][hs] = a1;
            part[prow + 2][hs] = a2;
            part[prow + 3][hs] = a3;
        }
        __syncthreads();   // S2

        // Phase 3: reduce partials
        {
            float4 p = *(const float4*)&part[row][sub << 2];
            float sv = (p.x + p.y) + (p.z + p.w);
            sv += __shfl_xor_sync(0xffffffffu, sv, 1);
            sv += __shfl_xor_sync(0xffffffffu, sv, 2);
            sv += __shfl_xor_sync(0xffffffffu, sv, 4);
            sv += __shfl_xor_sync(0xffffffffu, sv, 8);
            if (sub == 0) zbuf[row] = sv + gcur;
        }
        __syncthreads();   // S3

        // Phase 4: gates (MUFU.TANH) + state update + PUBLISH
        if (tid < 8) {
            int dU = tid >> 2, hU = tid & 3;
            int zb = dU << 4;
            float zi = zbuf[zb + hU];
            float zf = zbuf[zb + 4 + hU];
            float zg = zbuf[zb + 8 + hU];
            float zo = zbuf[zb + 12 + hU];
            float ig = hsigmoid(zi);
            float fg = hsigmoid(zf);
            float gg = htanh(zg);
            float oo = hsigmoid(zo);
            cst = fmaf(fg, cst, ig * gg);
            hv  = oo * htanh(cst);

            int e = cta * HC + hU;
            unsigned long long pk =
                (((unsigned long long)(unsigned)(s + 2)) << 32) |
                (unsigned long long)__float_as_uint(hv);
            st_rel(&g_hbuf[dU][(s + 1) & 1][e], pk);
        }
        __syncthreads();   // S4 — hold poll flood until all publishes issued

        // Phase 5 (off critical path): output store + next gate prefetch
        if (tid < 8) {
            int dU = tid >> 2, hU = tid & 3;
            int e  = cta * HC + hU;
            size_t orow = dU ? (size_t)(s ^ 7) : (size_t)s;
            out[orow * (2 * HID) + dU * HID + e] = hv;
            if (s == NSTEP - 1) {
                out[(size_t)NSTEP * 2 * HID + dU * HID + e] = hv;
                out[(size_t)NSTEP * 2 * HID + 2 * HID + dU * HID + e] = cst;
            }
        }
        if (sub == 0) {
            int ns = (s + 1 < NSTEP) ? (s + 1) : (NSTEP - 1);
            gcur = __ldg(g_gates + gq_base + (size_t)ns * G4H);
        }
    }
}

// ---------------------------------------------------------------------------
extern "C" void kernel_launch(void* const* d_in, const int* in_sizes, int n_in,
                              void* d_out, int out_size)
{
    const float* x   = (const float*)d_in[0];
    const float* h0  = (const float*)d_in[1];
    const float* c0  = (const float*)d_in[2];
    const float* Wif = (const float*)d_in[3];
    const float* Whf = (const float*)d_in[4];
    const float* bf  = (const float*)d_in[5];
    const float* Wib = (const float*)d_in[6];
    const float* Whb = (const float*)d_in[7];
    const float* bb  = (const float*)d_in[8];
    float* out = (float*)d_out;

    dim3 ggrid(G4H / BN, NSTEP / BM, 2);
    gates_gemm<<<ggrid, 256>>>(x, Wif, bf, Wib, bb);
    lstm_scan<<<NC, SCAN_THREADS>>>(h0, c0, Whf, Whb, out);
}